// round 12
// baseline (speedup 1.0000x reference)
#include <cuda_runtime.h>
#include <math.h>

#define BH   64
#define S    4096
#define D    64
#define NT   512
#define K    512
#define SIDX(a) ((a) + ((a) >> 3))
#define PIDX(e) ((e) + ((e) >> 5))          // twiddle-table anti-bank-conflict padding

// Static scratch (allocation-free rule: __device__ globals)
__device__ float2 g_x[(size_t)BH * D * S];    // packed q + i*k, layout [bh][d][s]
__device__ float  g_wk[(size_t)BH * D * K];   // top-K sorted softmax weights per column (8 MB)

// ---------------- packed f32x2 complex helpers ----------------
union f2u { float2 f; unsigned long long u; };

__device__ __forceinline__ float2 padd(float2 a, float2 b) {
    f2u A, B, R; A.f = a; B.f = b;
    asm("add.rn.f32x2 %0, %1, %2;" : "=l"(R.u) : "l"(A.u), "l"(B.u));
    return R.f;
}
__device__ __forceinline__ float2 psub(float2 a, float2 b) {
    f2u A, B, R, M; A.f = a; B.f = b; M.f = make_float2(-1.f, -1.f);
    asm("fma.rn.f32x2 %0, %1, %2, %3;" : "=l"(R.u) : "l"(B.u), "l"(M.u), "l"(A.u));
    return R.f;
}
__device__ __forceinline__ float2 cmul(float2 a, float2 b) {
    return make_float2(fmaf(a.x, b.x, -a.y * b.y), fmaf(a.x, b.y, a.y * b.x));
}
__device__ __forceinline__ float2 cconj(float2 a) { return make_float2(a.x, -a.y); }

// W_4096^e for e in [0, 4096): padded table of 1024 + rotation by (-i)^(e>>10)
__device__ __forceinline__ float2 twid(const float2* __restrict__ T, int e) {
    float2 t = T[PIDX(e & 1023)];
    int q = e >> 10;
    float2 r = t;
    if (q & 1) r = make_float2(r.y, -r.x);
    if (q & 2) r = make_float2(-r.x, -r.y);
    return r;
}

// octal-digit reversal of 12-bit index
__device__ __forceinline__ int rev8(int f) {
    return ((f & 7) << 9) | (((f >> 3) & 7) << 6) | (((f >> 6) & 7) << 3) | ((f >> 9) & 7);
}

// 8-point DFT in registers, natural-order outputs. SGN=-1 forward, +1 inverse.
template<int SGN>
__device__ __forceinline__ void dft8(float2 v[8]) {
    const float c = 0.70710678118654752f;
    float2 a0 = padd(v[0], v[4]), a4 = psub(v[0], v[4]);
    float2 a1 = padd(v[1], v[5]), a5 = psub(v[1], v[5]);
    float2 a2 = padd(v[2], v[6]), a6 = psub(v[2], v[6]);
    float2 a3 = padd(v[3], v[7]), a7 = psub(v[3], v[7]);
    a5 = cmul(a5, make_float2(c, SGN * c));
    a6 = (SGN < 0) ? make_float2(a6.y, -a6.x) : make_float2(-a6.y, a6.x);
    a7 = cmul(a7, make_float2(-c, SGN * c));
    float2 b0 = padd(a0, a2), b2 = psub(a0, a2);
    float2 b1 = padd(a1, a3), b3 = psub(a1, a3);
    b3 = (SGN < 0) ? make_float2(b3.y, -b3.x) : make_float2(-b3.y, b3.x);
    float2 e0 = padd(b0, b1), e1 = psub(b0, b1);
    float2 e2 = padd(b2, b3), e3 = psub(b2, b3);
    float2 d0 = padd(a4, a6), d2 = psub(a4, a6);
    float2 d1 = padd(a5, a7), d3 = psub(a5, a7);
    d3 = (SGN < 0) ? make_float2(d3.y, -d3.x) : make_float2(-d3.y, d3.x);
    float2 o0 = padd(d0, d1), o1 = psub(d0, d1);
    float2 o2 = padd(d2, d3), o3 = psub(d2, d3);
    v[0] = e0; v[4] = e1; v[2] = e2; v[6] = e3;
    v[1] = o0; v[5] = o1; v[3] = o2; v[7] = o3;
}

// 8x8 transpose among 8 consecutive lanes (cluster), 8 float2 regs/lane.
// Result: new_v[e] on member u  =  old_v[u] on member e.
__device__ __forceinline__ void cluster_transpose8(float2 v[8], int lane) {
#pragma unroll
    for (int m = 1; m < 8; m <<= 1) {
        bool hi = (lane & m) != 0;
#pragma unroll
        for (int j = 0; j < 8; j++)
            if ((j & m) == 0 && hi) { float2 t = v[j]; v[j] = v[j | m]; v[j | m] = t; }
#pragma unroll
        for (int j = 0; j < 8; j++)
            if (j & m) {
                f2u t; t.f = v[j];
                t.u = __shfl_xor_sync(0xffffffffu, t.u, m);
                v[j] = t.f;
            }
#pragma unroll
        for (int j = 0; j < 8; j++)
            if ((j & m) == 0 && hi) { float2 t = v[j]; v[j] = v[j | m]; v[j | m] = t; }
    }
}

// ---------------- transpose + pack:  [bh][s][d] -> [bh][d][s] as (q, k) float2 ----------------
__global__ void transpose_pack(const float* __restrict__ q, const float* __restrict__ k) {
    __shared__ float qt[32][33];
    __shared__ float kt[32][33];
    int bh = blockIdx.z;
    int s0 = blockIdx.x * 32;
    int d0 = blockIdx.y * 32;
    int tx = threadIdx.x, ty = threadIdx.y;
    const float* qb = q + (size_t)bh * S * D;
    const float* kb = k + (size_t)bh * S * D;
#pragma unroll
    for (int r = 0; r < 4; r++) {
        int s = s0 + ty + r * 8;
        qt[ty + r * 8][tx] = qb[(size_t)s * D + d0 + tx];
        kt[ty + r * 8][tx] = kb[(size_t)s * D + d0 + tx];
    }
    __syncthreads();
#pragma unroll
    for (int r = 0; r < 4; r++) {
        int d = d0 + ty + r * 8;
        int s = s0 + tx;
        g_x[((size_t)bh * D + d) * S + s] = make_float2(qt[tx][ty + r * 8], kt[tx][ty + r * 8]);
    }
}

// ---------------- per-series: radix-8 FFT -> cross-spectrum -> IFFT -> top-K select+sort -> softmax ----------------
__global__ __launch_bounds__(NT, 2) void fft_corr_sort() {
    __shared__ float2 sx[4640];                 // FFT buffer (SIDX layout) + NP layout for inv handoff
    __shared__ float2 s_tw[PIDX(1023) + 1];     // ~8.3 KB padded twiddles; reused for reduce + survivors
    __shared__ int scount;
    int tid = threadIdx.x;
    int lane = tid & 31;
    const float2* gx = g_x + (size_t)blockIdx.x * S;

    float2 v[8];
    // issue global loads first so their latency overlaps the table build
#pragma unroll
    for (int r = 0; r < 8; r++) v[r] = gx[tid + 512 * r];

    // precise twiddle table (padded layout)
#pragma unroll
    for (int k = tid; k < 1024; k += NT) {
        float sn, cs;
        sincospif(-(float)k / 2048.0f, &sn, &cs);
        s_tw[PIDX(k)] = make_float2(cs, sn);
    }
    __syncthreads();                       // twiddle table ready

    // ---- forward stage 0 : stride 512, p=tid ----
    dft8<-1>(v);
#pragma unroll
    for (int r = 1; r < 8; r++) v[r] = cmul(v[r], twid(s_tw, tid * r));
#pragma unroll
    for (int r = 0; r < 8; r++) sx[SIDX(tid + 512 * r)] = v[r];
    __syncthreads();
    // ---- forward stage 1 : stride 64 ----
    {
        int base = (tid >> 6) << 9, p = tid & 63;
#pragma unroll
        for (int r = 0; r < 8; r++) v[r] = sx[SIDX(base + p + 64 * r)];
        dft8<-1>(v);
#pragma unroll
        for (int r = 1; r < 8; r++) v[r] = cmul(v[r], twid(s_tw, (p * r) << 3));
#pragma unroll
        for (int r = 0; r < 8; r++) sx[SIDX(base + p + 64 * r)] = v[r];
    }
    __syncthreads();
    // ---- forward stages 2+3 merged: stage-2 in regs, shfl transpose, stage-3 in regs ----
    {
        int base = (tid >> 3) << 6, p = tid & 7;
#pragma unroll
        for (int r = 0; r < 8; r++) v[r] = sx[SIDX(base + p + 8 * r)];
        dft8<-1>(v);
#pragma unroll
        for (int r = 1; r < 8; r++) v[r] = cmul(v[r], twid(s_tw, (p * r) << 6));
        cluster_transpose8(v, lane);
        dft8<-1>(v);                       // stage 3, no twiddle
        // v[e] = spectrum (octal-reversed) at position 8*tid + e ; publish for partner reads
#pragma unroll
        for (int r = 0; r < 8; r++) sx[SIDX(8 * tid + r)] = v[r];
    }
    __syncthreads();

    // ---- cross-spectrum (own 8 positions, partner read only) + inverse stages 0+1 merged ----
    {
        float2 xp[8];
#pragma unroll
        for (int e = 0; e < 8; e++) {
            int j  = 8 * tid + e;
            int f  = rev8(j);
            int fp = (S - f) & (S - 1);
            xp[e] = sx[SIDX(rev8(fp))];
        }
#pragma unroll
        for (int e = 0; e < 8; e++) {
            float2 X = v[e], Xp = xp[e];
            float Qr = 0.5f * (X.x + Xp.x);
            float Qi = 0.5f * (X.y - Xp.y);
            float Kr = 0.5f * (X.y + Xp.y);
            float Ki = 0.5f * (Xp.x - X.x);
            v[e] = make_float2(Qr * Kr + Qi * Ki, Qi * Kr - Qr * Ki);
        }
        dft8<1>(v);                        // inverse stage 0 (contiguous 8, no twiddle)
        cluster_transpose8(v, lane);       // redistribute for stride-8 stage (cluster-local)
        int p = tid & 7;
#pragma unroll
        for (int r = 1; r < 8; r++) v[r] = cmul(v[r], cconj(twid(s_tw, (p * r) << 6)));
        dft8<1>(v);                        // inverse stage 1
        // Output position for register r: j = c*512 + b*64 + s1, with
        // c = tid>>6, b = (tid>>3)&7, s1 = (tid&7) + 8r.
        // Write into swizzled handoff layout N = (s1*8 + c) + 512*b, NP = N + (N>>3) + 4*(N>>9).
        int c1 = tid >> 6, b1 = (tid >> 3) & 7, d0 = tid & 7;
#pragma unroll
        for (int r = 0; r < 8; r++) {
            int s1 = d0 + 8 * r;
            int N  = (s1 << 3) + c1 + (b1 << 9);
            int NP = N + (N >> 3) + (b1 << 2);
            sx[NP] = v[r];
        }
    }
    __syncthreads();

    // ---- inverse stages 2+3 merged: inv2 (digit d2) in regs, shfl transpose, inv3 (digit d3) in regs ----
    float rv[8];
    {
        int s = tid >> 3, c = tid & 7;     // thread owns fixed (d3=c during inv2, s); register = d2
#pragma unroll
        for (int b = 0; b < 8; b++) {
            int N  = tid + (b << 9);
            int NP = N + (N >> 3) + (b << 2);
            v[b] = sx[NP];
        }
#pragma unroll
        for (int b = 1; b < 8; b++) v[b] = cmul(v[b], cconj(twid(s_tw, (s * b) << 3)));
        dft8<1>(v);                        // inverse stage 2 (over d2)
        cluster_transpose8(v, lane);       // lane-digit c (=d3) <-> register
        int t3 = c * 64 + s;               // within-512 offset (d2=c role, s)
#pragma unroll
        for (int e = 1; e < 8; e++) v[e] = cmul(v[e], cconj(twid(s_tw, t3 * e)));
        dft8<1>(v);                        // inverse stage 3 (over d3)
        const float invN = 1.0f / (float)S;
#pragma unroll
        for (int e = 0; e < 8; e++) rv[e] = v[e].x * invN;   // arbitrary permutation: selection is order-free
    }
    __syncthreads();                        // all sx / s_tw reads done; reuse s_tw region

    float* red  = (float*)s_tw;             // [0..32) reduction scratch
    float* surv = ((float*)s_tw) + 1024;    // [1024..1536) survivor list (512 floats)

    // ---- block max m ----
    float m = rv[0];
#pragma unroll
    for (int e = 1; e < 8; e++) m = fmaxf(m, rv[e]);
#pragma unroll
    for (int o = 16; o > 0; o >>= 1) m = fmaxf(m, __shfl_xor_sync(0xffffffffu, m, o));
    if ((tid & 31) == 0) red[tid >> 5] = m;
    __syncthreads();
    m = red[0];
#pragma unroll
    for (int i = 1; i < NT / 32; i++) m = fmaxf(m, red[i]);

    // ---- Z over all 4096 (order-free; __expf FTZ zeros the deep tail) ----
    float part = 0.f;
#pragma unroll
    for (int e = 0; e < 8; e++) part += __expf(rv[e] - m);
#pragma unroll
    for (int o = 16; o > 0; o >>= 1) part += __shfl_xor_sync(0xffffffffu, part, o);
    if ((tid & 31) == 0) red[16 + (tid >> 5)] = part;
    if (tid == 0) scount = 0;
    __syncthreads();
    float Z = 0.f;
#pragma unroll
    for (int i = 0; i < NT / 32; i++) Z += red[16 + i];
    float invZ = 1.0f / Z;

    // ---- compact survivors (v >= m-95; anything below has __expf == 0 identically) ----
    float thresh = m - 95.0f;
#pragma unroll
    for (int e = 0; e < 8; e++) {
        if (rv[e] >= thresh) {
            int p = atomicAdd(&scount, 1);
            if (p < K) surv[p] = rv[e];
        }
    }
    __syncthreads();
    int C = scount;
    for (int i = tid; i < K; i += NT) if (i >= C) surv[i] = -INFINITY;
    __syncthreads();

    // ---- bitonic sort 512 survivors descending: 2 warps, 8 elems/thread, 1 smem pass ----
    float sv[8];
    const bool sorter = (tid < 64);
    if (sorter) {
#pragma unroll
        for (int e = 0; e < 8; e++) sv[e] = surv[8 * tid + e];
#pragma unroll 1
        for (int k2 = 2; k2 <= 256; k2 <<= 1) {
            int jhi = (k2 >> 1) > 128 ? 128 : (k2 >> 1);
#pragma unroll 1
            for (int j2 = jhi; j2 >= 8; j2 >>= 1) {
                int msk = j2 >> 3;
                bool lo = ((tid & msk) == 0);
#pragma unroll
                for (int e = 0; e < 8; e++) {
                    float b = __shfl_xor_sync(0xffffffffu, sv[e], msk);
                    int i = 8 * tid + e;
                    bool up = ((i & k2) == 0);
                    sv[e] = (up == lo) ? fmaxf(sv[e], b) : fminf(sv[e], b);
                }
            }
            int jr = (k2 >> 1) < 4 ? (k2 >> 1) : 4;
#pragma unroll 1
            for (int j2 = jr; j2 >= 1; j2 >>= 1) {
#pragma unroll
                for (int e = 0; e < 8; e++) {
                    if ((e & j2) == 0) {
                        int i = 8 * tid + e;
                        bool up = ((i & k2) == 0);
                        float a = sv[e], b = sv[e | j2];
                        sv[e]      = up ? fmaxf(a, b) : fminf(a, b);
                        sv[e | j2] = up ? fminf(a, b) : fmaxf(a, b);
                    }
                }
            }
        }
#pragma unroll
        for (int e = 0; e < 8; e++) surv[8 * tid + e] = sv[e];
    }
    __syncthreads();
    if (sorter) {
#pragma unroll
        for (int e = 0; e < 8; e++) {
            int i = 8 * tid + e;
            float b = surv[i ^ 256];
            bool lo = ((i & 256) == 0);
            sv[e] = lo ? fmaxf(sv[e], b) : fminf(sv[e], b);   // k2=512: descending merge
        }
#pragma unroll 1
        for (int j2 = 128; j2 >= 8; j2 >>= 1) {
            int msk = j2 >> 3;
            bool lo = ((tid & msk) == 0);
#pragma unroll
            for (int e = 0; e < 8; e++) {
                float b = __shfl_xor_sync(0xffffffffu, sv[e], msk);
                sv[e] = lo ? fmaxf(sv[e], b) : fminf(sv[e], b);
            }
        }
#pragma unroll 1
        for (int j2 = 4; j2 >= 1; j2 >>= 1) {
#pragma unroll
            for (int e = 0; e < 8; e++) {
                if ((e & j2) == 0) {
                    float a = sv[e], b = sv[e | j2];
                    sv[e] = fmaxf(a, b); sv[e | j2] = fminf(a, b);
                }
            }
        }
    }
    __syncthreads();                        // all cross-warp surv reads done
    if (sorter) {
#pragma unroll
        for (int e = 0; e < 8; e++) surv[8 * tid + e] = sv[e];
    }
    __syncthreads();

    // ---- write top-K softmax weights (one per thread, coalesced) ----
    g_wk[(size_t)blockIdx.x * K + tid] = __expf(surv[tid] - m) * invZ;
}

// ---------------- out[bh,i,l] = sum_j Wk[bh,j,i] * V[bh,j,l] for i<K ; zeros for i>=K ----------------
__global__ __launch_bounds__(256) void wgemm(const float* __restrict__ v, float* __restrict__ out) {
    __shared__ float Vs[D * D];
    __shared__ float Ws[D][128];
    int bh  = blockIdx.y;
    int i0  = blockIdx.x * 128;             // blockIdx.x in [0, S/128)
    int tid = threadIdx.x;

    if (i0 >= K) {                          // ranks >= K have softmax weight identically 0
        float4 z = make_float4(0.f, 0.f, 0.f, 0.f);
        float4* ob = (float4*)(out + ((size_t)bh * S + i0) * D);
#pragma unroll
        for (int p = 0; p < (128 * D / 4) / 256; p++) ob[tid + p * 256] = z;
        return;
    }

    const float* vb = v + (size_t)bh * S * D;
#pragma unroll
    for (int p = 0; p < (D * D) / 256; p++) Vs[tid + p * 256] = vb[tid + p * 256];
    const float* wb = g_wk + (size_t)bh * D * K + i0;
#pragma unroll
    for (int p = 0; p < (D * 128) / 256; p++) {
        int q = tid + p * 256;
        int j = q >> 7, i = q & 127;
        Ws[j][i] = wb[(size_t)j * K + i];
    }
    __syncthreads();
    int il = tid & 15, ir = tid >> 4;
    float acc[8][4];
#pragma unroll
    for (int a = 0; a < 8; a++)
#pragma unroll
        for (int b = 0; b < 4; b++) acc[a][b] = 0.f;
#pragma unroll 4
    for (int j = 0; j < D; j++) {
        float4 vl = *(const float4*)&Vs[j * D + il * 4];
        float4 w0 = *(const float4*)&Ws[j][ir * 8];
        float4 w1 = *(const float4*)&Ws[j][ir * 8 + 4];
        float wv[8] = {w0.x, w0.y, w0.z, w0.w, w1.x, w1.y, w1.z, w1.w};
#pragma unroll
        for (int a = 0; a < 8; a++) {
            acc[a][0] += wv[a] * vl.x;
            acc[a][1] += wv[a] * vl.y;
            acc[a][2] += wv[a] * vl.z;
            acc[a][3] += wv[a] * vl.w;
        }
    }
    float* ob = out + ((size_t)bh * S + i0) * D;
#pragma unroll
    for (int a = 0; a < 8; a++) {
        float4 o = make_float4(acc[a][0], acc[a][1], acc[a][2], acc[a][3]);
        *(float4*)&ob[(size_t)(ir * 8 + a) * D + il * 4] = o;
    }
}

extern "C" void kernel_launch(void* const* d_in, const int* in_sizes, int n_in,
                              void* d_out, int out_size) {
    const float* q = (const float*)d_in[0];
    const float* k = (const float*)d_in[1];
    const float* v = (const float*)d_in[2];
    float* out = (float*)d_out;

    dim3 tb(32, 8);
    dim3 tg(S / 32, D / 32, BH);
    transpose_pack<<<tg, tb>>>(q, k);

    fft_corr_sort<<<BH * D, NT>>>();

    dim3 gg(S / 128, BH);
    wgemm<<<gg, 256>>>(v, out);
}

// round 13
// speedup vs baseline: 1.0174x; 1.0174x over previous
#include <cuda_runtime.h>
#include <math.h>

#define BH   64
#define S    4096
#define D    64
#define NT   512
#define K    512
#define SIDX(a) ((a) + ((a) >> 3))
#define PIDX(e) ((e) + ((e) >> 5))          // twiddle-table anti-bank-conflict padding

// Static scratch (allocation-free rule: __device__ globals)
__device__ float2 g_x[(size_t)BH * D * S];    // packed q + i*k, layout [bh][d][s]
__device__ float  g_wk[(size_t)BH * D * K];   // top-K sorted softmax weights per column (8 MB)
__device__ float2 g_twg[1024];                // precomputed W_4096^k, k in [0,1024)

// ---------------- packed f32x2 complex helpers ----------------
union f2u { float2 f; unsigned long long u; };

__device__ __forceinline__ float2 padd(float2 a, float2 b) {
    f2u A, B, R; A.f = a; B.f = b;
    asm("add.rn.f32x2 %0, %1, %2;" : "=l"(R.u) : "l"(A.u), "l"(B.u));
    return R.f;
}
__device__ __forceinline__ float2 psub(float2 a, float2 b) {
    f2u A, B, R, M; A.f = a; B.f = b; M.f = make_float2(-1.f, -1.f);
    asm("fma.rn.f32x2 %0, %1, %2, %3;" : "=l"(R.u) : "l"(B.u), "l"(M.u), "l"(A.u));
    return R.f;
}
__device__ __forceinline__ float2 cmul(float2 a, float2 b) {
    return make_float2(fmaf(a.x, b.x, -a.y * b.y), fmaf(a.x, b.y, a.y * b.x));
}
__device__ __forceinline__ float2 cconj(float2 a) { return make_float2(a.x, -a.y); }

// W_4096^e for e in [0, 4096): padded table of 1024 + rotation by (-i)^(e>>10)
__device__ __forceinline__ float2 twid(const float2* __restrict__ T, int e) {
    float2 t = T[PIDX(e & 1023)];
    int q = e >> 10;
    float2 r = t;
    if (q & 1) r = make_float2(r.y, -r.x);
    if (q & 2) r = make_float2(-r.x, -r.y);
    return r;
}

// octal-digit reversal of 12-bit index
__device__ __forceinline__ int rev8(int f) {
    return ((f & 7) << 9) | (((f >> 3) & 7) << 6) | (((f >> 6) & 7) << 3) | ((f >> 9) & 7);
}

// 8-point DFT in registers, natural-order outputs. SGN=-1 forward, +1 inverse.
template<int SGN>
__device__ __forceinline__ void dft8(float2 v[8]) {
    const float c = 0.70710678118654752f;
    float2 a0 = padd(v[0], v[4]), a4 = psub(v[0], v[4]);
    float2 a1 = padd(v[1], v[5]), a5 = psub(v[1], v[5]);
    float2 a2 = padd(v[2], v[6]), a6 = psub(v[2], v[6]);
    float2 a3 = padd(v[3], v[7]), a7 = psub(v[3], v[7]);
    a5 = cmul(a5, make_float2(c, SGN * c));
    a6 = (SGN < 0) ? make_float2(a6.y, -a6.x) : make_float2(-a6.y, a6.x);
    a7 = cmul(a7, make_float2(-c, SGN * c));
    float2 b0 = padd(a0, a2), b2 = psub(a0, a2);
    float2 b1 = padd(a1, a3), b3 = psub(a1, a3);
    b3 = (SGN < 0) ? make_float2(b3.y, -b3.x) : make_float2(-b3.y, b3.x);
    float2 e0 = padd(b0, b1), e1 = psub(b0, b1);
    float2 e2 = padd(b2, b3), e3 = psub(b2, b3);
    float2 d0 = padd(a4, a6), d2 = psub(a4, a6);
    float2 d1 = padd(a5, a7), d3 = psub(a5, a7);
    d3 = (SGN < 0) ? make_float2(d3.y, -d3.x) : make_float2(-d3.y, d3.x);
    float2 o0 = padd(d0, d1), o1 = psub(d0, d1);
    float2 o2 = padd(d2, d3), o3 = psub(d2, d3);
    v[0] = e0; v[4] = e1; v[2] = e2; v[6] = e3;
    v[1] = o0; v[5] = o1; v[3] = o2; v[7] = o3;
}

// 8x8 transpose among 8 consecutive lanes (cluster), 8 float2 regs/lane.
__device__ __forceinline__ void cluster_transpose8(float2 v[8], int lane) {
#pragma unroll
    for (int m = 1; m < 8; m <<= 1) {
        bool hi = (lane & m) != 0;
#pragma unroll
        for (int j = 0; j < 8; j++)
            if ((j & m) == 0 && hi) { float2 t = v[j]; v[j] = v[j | m]; v[j | m] = t; }
#pragma unroll
        for (int j = 0; j < 8; j++)
            if (j & m) {
                f2u t; t.f = v[j];
                t.u = __shfl_xor_sync(0xffffffffu, t.u, m);
                v[j] = t.f;
            }
#pragma unroll
        for (int j = 0; j < 8; j++)
            if ((j & m) == 0 && hi) { float2 t = v[j]; v[j] = v[j | m]; v[j | m] = t; }
    }
}

// ---------------- one-off: precompute twiddle table ----------------
__global__ void twinit() {
    int k = blockIdx.x * 512 + threadIdx.x;
    float sn, cs;
    sincospif(-(float)k / 2048.0f, &sn, &cs);
    g_twg[k] = make_float2(cs, sn);
}

// ---------------- transpose + pack:  [bh][s][d] -> [bh][d][s] as (q, k) float2 ----------------
__global__ void transpose_pack(const float* __restrict__ q, const float* __restrict__ k) {
    __shared__ float qt[32][33];
    __shared__ float kt[32][33];
    int bh = blockIdx.z;
    int s0 = blockIdx.x * 32;
    int d0 = blockIdx.y * 32;
    int tx = threadIdx.x, ty = threadIdx.y;
    const float* qb = q + (size_t)bh * S * D;
    const float* kb = k + (size_t)bh * S * D;
#pragma unroll
    for (int r = 0; r < 4; r++) {
        int s = s0 + ty + r * 8;
        qt[ty + r * 8][tx] = qb[(size_t)s * D + d0 + tx];
        kt[ty + r * 8][tx] = kb[(size_t)s * D + d0 + tx];
    }
    __syncthreads();
#pragma unroll
    for (int r = 0; r < 4; r++) {
        int d = d0 + ty + r * 8;
        int s = s0 + tx;
        g_x[((size_t)bh * D + d) * S + s] = make_float2(qt[tx][ty + r * 8], kt[tx][ty + r * 8]);
    }
}

// ---------------- per-series: radix-8 FFT -> cross-spectrum -> IFFT -> top-K select+sort -> softmax ----------------
__global__ __launch_bounds__(NT, 2) void fft_corr_sort() {
    __shared__ float2 sx[SIDX(S - 1) + 1];      // ~36.9 KB (padded)
    __shared__ float2 s_tw[PIDX(1023) + 1];     // ~8.3 KB padded twiddles; reused for reduce + survivors
    __shared__ int scount;
    int tid = threadIdx.x;
    int lane = tid & 31;
    const float2* gx = g_x + (size_t)blockIdx.x * S;

    float2 v[8];
    // issue global loads first so their latency overlaps the table load
#pragma unroll
    for (int r = 0; r < 8; r++) v[r] = gx[tid + 512 * r];

    // load precomputed twiddle table (L2-resident after first wave)
#pragma unroll
    for (int k = tid; k < 1024; k += NT) s_tw[PIDX(k)] = g_twg[k];
    __syncthreads();                       // twiddle table ready

    // ---- forward stage 0 : stride 512, p=tid ----
    dft8<-1>(v);
#pragma unroll
    for (int r = 1; r < 8; r++) v[r] = cmul(v[r], twid(s_tw, tid * r));
#pragma unroll
    for (int r = 0; r < 8; r++) sx[SIDX(tid + 512 * r)] = v[r];
    __syncthreads();
    // ---- forward stage 1 : stride 64 ----
    {
        int base = (tid >> 6) << 9, p = tid & 63;
#pragma unroll
        for (int r = 0; r < 8; r++) v[r] = sx[SIDX(base + p + 64 * r)];
        dft8<-1>(v);
#pragma unroll
        for (int r = 1; r < 8; r++) v[r] = cmul(v[r], twid(s_tw, (p * r) << 3));
#pragma unroll
        for (int r = 0; r < 8; r++) sx[SIDX(base + p + 64 * r)] = v[r];
    }
    __syncthreads();
    // ---- forward stages 2+3 merged: stage-2 in regs, shfl transpose, stage-3 in regs ----
    {
        int base = (tid >> 3) << 6, p = tid & 7;
#pragma unroll
        for (int r = 0; r < 8; r++) v[r] = sx[SIDX(base + p + 8 * r)];
        dft8<-1>(v);
#pragma unroll
        for (int r = 1; r < 8; r++) v[r] = cmul(v[r], twid(s_tw, (p * r) << 6));
        cluster_transpose8(v, lane);
        dft8<-1>(v);                       // stage 3, no twiddle
        // v[e] = spectrum (octal-reversed) at position 8*tid + e ; publish for partner reads
#pragma unroll
        for (int r = 0; r < 8; r++) sx[SIDX(8 * tid + r)] = v[r];
    }
    __syncthreads();

    // ---- cross-spectrum (own 8 positions, partner read only) + inverse stages 0+1 merged ----
    {
        float2 xp[8];
#pragma unroll
        for (int e = 0; e < 8; e++) {
            int j  = 8 * tid + e;
            int f  = rev8(j);
            int fp = (S - f) & (S - 1);
            xp[e] = sx[SIDX(rev8(fp))];
        }
#pragma unroll
        for (int e = 0; e < 8; e++) {
            float2 X = v[e], Xp = xp[e];
            float Qr = 0.5f * (X.x + Xp.x);
            float Qi = 0.5f * (X.y - Xp.y);
            float Kr = 0.5f * (X.y + Xp.y);
            float Ki = 0.5f * (Xp.x - X.x);
            v[e] = make_float2(Qr * Kr + Qi * Ki, Qi * Kr - Qr * Ki);
        }
        dft8<1>(v);                        // inverse stage 0 (contiguous 8, no twiddle)
        cluster_transpose8(v, lane);       // redistribute for stride-8 stage (cluster-local)
        int p = tid & 7;
#pragma unroll
        for (int r = 1; r < 8; r++) v[r] = cmul(v[r], cconj(twid(s_tw, (p * r) << 6)));
        dft8<1>(v);                        // inverse stage 1
        int base = (tid >> 3) << 6;
#pragma unroll
        for (int r = 0; r < 8; r++) sx[SIDX(base + p + 8 * r)] = v[r];
    }
    __syncthreads();
    // ---- inverse stage 2 : stride 64 ----
    {
        int base = (tid >> 6) << 9, p = tid & 63;
#pragma unroll
        for (int r = 0; r < 8; r++) v[r] = sx[SIDX(base + p + 64 * r)];
#pragma unroll
        for (int r = 1; r < 8; r++) v[r] = cmul(v[r], cconj(twid(s_tw, (p * r) << 3)));
        dft8<1>(v);
#pragma unroll
        for (int r = 0; r < 8; r++) sx[SIDX(base + p + 64 * r)] = v[r];
    }
    __syncthreads();

    // ---- inverse stage 3 : stride 512 ; corr stays in registers ----
    float rv[8];
    {
        const float invN = 1.0f / (float)S;
#pragma unroll
        for (int r = 0; r < 8; r++) v[r] = sx[SIDX(tid + 512 * r)];
#pragma unroll
        for (int r = 1; r < 8; r++) v[r] = cmul(v[r], cconj(twid(s_tw, tid * r)));
        dft8<1>(v);
#pragma unroll
        for (int r = 0; r < 8; r++) rv[r] = v[r].x * invN;
    }
    __syncthreads();                        // all sx / s_tw reads done; reuse s_tw region

    float* red  = (float*)s_tw;             // [0..32) reduction scratch
    float* surv = ((float*)s_tw) + 1024;    // [1024..1536) survivor list (512 floats)

    // ---- block max m ----
    float m = rv[0];
#pragma unroll
    for (int e = 1; e < 8; e++) m = fmaxf(m, rv[e]);
#pragma unroll
    for (int o = 16; o > 0; o >>= 1) m = fmaxf(m, __shfl_xor_sync(0xffffffffu, m, o));
    if ((tid & 31) == 0) red[tid >> 5] = m;
    __syncthreads();
    m = red[0];
#pragma unroll
    for (int i = 1; i < NT / 32; i++) m = fmaxf(m, red[i]);

    // ---- Z over all 4096 (order-free; __expf FTZ zeros the deep tail) ----
    float part = 0.f;
#pragma unroll
    for (int e = 0; e < 8; e++) part += __expf(rv[e] - m);
#pragma unroll
    for (int o = 16; o > 0; o >>= 1) part += __shfl_xor_sync(0xffffffffu, part, o);
    if ((tid & 31) == 0) red[16 + (tid >> 5)] = part;
    if (tid == 0) scount = 0;
    __syncthreads();
    float Z = 0.f;
#pragma unroll
    for (int i = 0; i < NT / 32; i++) Z += red[16 + i];
    float invZ = 1.0f / Z;

    // ---- compact survivors (v >= m-95; anything below has __expf == 0 identically) ----
    float thresh = m - 95.0f;
#pragma unroll
    for (int e = 0; e < 8; e++) {
        if (rv[e] >= thresh) {
            int p = atomicAdd(&scount, 1);
            if (p < K) surv[p] = rv[e];
        }
    }
    __syncthreads();
    int C = scount;
    for (int i = tid; i < K; i += NT) if (i >= C) surv[i] = -INFINITY;
    __syncthreads();

    // ---- bitonic sort 512 survivors descending: 2 warps, 8 elems/thread, 1 smem pass ----
    float sv[8];
    const bool sorter = (tid < 64);
    if (sorter) {
#pragma unroll
        for (int e = 0; e < 8; e++) sv[e] = surv[8 * tid + e];
#pragma unroll 1
        for (int k2 = 2; k2 <= 256; k2 <<= 1) {
            int jhi = (k2 >> 1) > 128 ? 128 : (k2 >> 1);
#pragma unroll 1
            for (int j2 = jhi; j2 >= 8; j2 >>= 1) {
                int msk = j2 >> 3;
                bool lo = ((tid & msk) == 0);
#pragma unroll
                for (int e = 0; e < 8; e++) {
                    float b = __shfl_xor_sync(0xffffffffu, sv[e], msk);
                    int i = 8 * tid + e;
                    bool up = ((i & k2) == 0);
                    sv[e] = (up == lo) ? fmaxf(sv[e], b) : fminf(sv[e], b);
                }
            }
            int jr = (k2 >> 1) < 4 ? (k2 >> 1) : 4;
#pragma unroll 1
            for (int j2 = jr; j2 >= 1; j2 >>= 1) {
#pragma unroll
                for (int e = 0; e < 8; e++) {
                    if ((e & j2) == 0) {
                        int i = 8 * tid + e;
                        bool up = ((i & k2) == 0);
                        float a = sv[e], b = sv[e | j2];
                        sv[e]      = up ? fmaxf(a, b) : fminf(a, b);
                        sv[e | j2] = up ? fminf(a, b) : fmaxf(a, b);
                    }
                }
            }
        }
#pragma unroll
        for (int e = 0; e < 8; e++) surv[8 * tid + e] = sv[e];
    }
    __syncthreads();
    if (sorter) {
#pragma unroll
        for (int e = 0; e < 8; e++) {
            int i = 8 * tid + e;
            float b = surv[i ^ 256];
            bool lo = ((i & 256) == 0);
            sv[e] = lo ? fmaxf(sv[e], b) : fminf(sv[e], b);   // k2=512: descending merge
        }
#pragma unroll 1
        for (int j2 = 128; j2 >= 8; j2 >>= 1) {
            int msk = j2 >> 3;
            bool lo = ((tid & msk) == 0);
#pragma unroll
            for (int e = 0; e < 8; e++) {
                float b = __shfl_xor_sync(0xffffffffu, sv[e], msk);
                sv[e] = lo ? fmaxf(sv[e], b) : fminf(sv[e], b);
            }
        }
#pragma unroll 1
        for (int j2 = 4; j2 >= 1; j2 >>= 1) {
#pragma unroll
            for (int e = 0; e < 8; e++) {
                if ((e & j2) == 0) {
                    float a = sv[e], b = sv[e | j2];
                    sv[e] = fmaxf(a, b); sv[e | j2] = fminf(a, b);
                }
            }
        }
        // ---- sorted values live here in registers: write weights straight out ----
        float4 o0 = make_float4(__expf(sv[0] - m) * invZ, __expf(sv[1] - m) * invZ,
                                __expf(sv[2] - m) * invZ, __expf(sv[3] - m) * invZ);
        float4 o1 = make_float4(__expf(sv[4] - m) * invZ, __expf(sv[5] - m) * invZ,
                                __expf(sv[6] - m) * invZ, __expf(sv[7] - m) * invZ);
        float* gw = g_wk + (size_t)blockIdx.x * K + 8 * tid;
        *(float4*)(gw)     = o0;
        *(float4*)(gw + 4) = o1;
    }
}

// ---------------- out[bh,i,l] = sum_j Wk[bh,j,i] * V[bh,j,l] for i<K ; zeros for i>=K ----------------
__global__ __launch_bounds__(256) void wgemm(const float* __restrict__ v, float* __restrict__ out) {
    __shared__ float Vs[D * D];
    __shared__ float Ws[D][128];
    int bh  = blockIdx.y;
    int i0  = blockIdx.x * 128;             // blockIdx.x in [0, S/128)
    int tid = threadIdx.x;

    if (i0 >= K) {                          // ranks >= K have softmax weight identically 0
        float4 z = make_float4(0.f, 0.f, 0.f, 0.f);
        float4* ob = (float4*)(out + ((size_t)bh * S + i0) * D);
#pragma unroll
        for (int p = 0; p < (128 * D / 4) / 256; p++) ob[tid + p * 256] = z;
        return;
    }

    const float* vb = v + (size_t)bh * S * D;
#pragma unroll
    for (int p = 0; p < (D * D) / 256; p++) Vs[tid + p * 256] = vb[tid + p * 256];
    const float* wb = g_wk + (size_t)bh * D * K + i0;
#pragma unroll
    for (int p = 0; p < (D * 128) / 256; p++) {
        int q = tid + p * 256;
        int j = q >> 7, i = q & 127;
        Ws[j][i] = wb[(size_t)j * K + i];
    }
    __syncthreads();
    int il = tid & 15, ir = tid >> 4;
    float acc[8][4];
#pragma unroll
    for (int a = 0; a < 8; a++)
#pragma unroll
        for (int b = 0; b < 4; b++) acc[a][b] = 0.f;
#pragma unroll 4
    for (int j = 0; j < D; j++) {
        float4 vl = *(const float4*)&Vs[j * D + il * 4];
        float4 w0 = *(const float4*)&Ws[j][ir * 8];
        float4 w1 = *(const float4*)&Ws[j][ir * 8 + 4];
        float wv[8] = {w0.x, w0.y, w0.z, w0.w, w1.x, w1.y, w1.z, w1.w};
#pragma unroll
        for (int a = 0; a < 8; a++) {
            acc[a][0] += wv[a] * vl.x;
            acc[a][1] += wv[a] * vl.y;
            acc[a][2] += wv[a] * vl.z;
            acc[a][3] += wv[a] * vl.w;
        }
    }
    float* ob = out + ((size_t)bh * S + i0) * D;
#pragma unroll
    for (int a = 0; a < 8; a++) {
        float4 o = make_float4(acc[a][0], acc[a][1], acc[a][2], acc[a][3]);
        *(float4*)&ob[(size_t)(ir * 8 + a) * D + il * 4] = o;
    }
}

extern "C" void kernel_launch(void* const* d_in, const int* in_sizes, int n_in,
                              void* d_out, int out_size) {
    const float* q = (const float*)d_in[0];
    const float* k = (const float*)d_in[1];
    const float* v = (const float*)d_in[2];
    float* out = (float*)d_out;

    twinit<<<2, 512>>>();

    dim3 tb(32, 8);
    dim3 tg(S / 32, D / 32, BH);
    transpose_pack<<<tg, tb>>>(q, k);

    fft_corr_sort<<<BH * D, NT>>>();

    dim3 gg(S / 128, BH);
    wgemm<<<gg, 256>>>(v, out);
}

// round 14
// speedup vs baseline: 1.4422x; 1.4176x over previous
#include <cuda_runtime.h>
#include <math.h>

#define BH   64
#define S    4096
#define D    64
#define NT   512
#define K    512
#define SIDX(a) ((a) + ((a) >> 3))
#define PIDX(e) ((e) + ((e) >> 5))          // twiddle-table anti-bank-conflict padding

// Static scratch (allocation-free rule: __device__ globals)
__device__ float2 g_x[(size_t)BH * D * S];    // packed q + i*k, layout [bh][d][s]
__device__ float  g_wk[(size_t)BH * D * K];   // top-K sorted softmax weights per column (8 MB)
__device__ float2 g_twg[1024];                // precomputed W_4096^k, k in [0,1024)

// ---------------- packed f32x2 complex helpers ----------------
union f2u { float2 f; unsigned long long u; };

__device__ __forceinline__ float2 padd(float2 a, float2 b) {
    f2u A, B, R; A.f = a; B.f = b;
    asm("add.rn.f32x2 %0, %1, %2;" : "=l"(R.u) : "l"(A.u), "l"(B.u));
    return R.f;
}
__device__ __forceinline__ float2 psub(float2 a, float2 b) {
    f2u A, B, R, M; A.f = a; B.f = b; M.f = make_float2(-1.f, -1.f);
    asm("fma.rn.f32x2 %0, %1, %2, %3;" : "=l"(R.u) : "l"(B.u), "l"(M.u), "l"(A.u));
    return R.f;
}
__device__ __forceinline__ float2 cmul(float2 a, float2 b) {
    return make_float2(fmaf(a.x, b.x, -a.y * b.y), fmaf(a.x, b.y, a.y * b.x));
}
__device__ __forceinline__ float2 cconj(float2 a) { return make_float2(a.x, -a.y); }

// named 64-thread barrier for group g (warps 2g, 2g+1); ids 1..8 (0 is __syncthreads)
__device__ __forceinline__ void barg(int g) {
    asm volatile("bar.sync %0, 64;" :: "r"(g + 1) : "memory");
}

// W_4096^e for e in [0, 4096): padded table of 1024 + rotation by (-i)^(e>>10)
__device__ __forceinline__ float2 twid(const float2* __restrict__ T, int e) {
    float2 t = T[PIDX(e & 1023)];
    int q = e >> 10;
    float2 r = t;
    if (q & 1) r = make_float2(r.y, -r.x);
    if (q & 2) r = make_float2(-r.x, -r.y);
    return r;
}

// octal-digit reversal of 12-bit index
__device__ __forceinline__ int rev8(int f) {
    return ((f & 7) << 9) | (((f >> 3) & 7) << 6) | (((f >> 6) & 7) << 3) | ((f >> 9) & 7);
}

// 8-point DFT in registers, natural-order outputs. SGN=-1 forward, +1 inverse.
template<int SGN>
__device__ __forceinline__ void dft8(float2 v[8]) {
    const float c = 0.70710678118654752f;
    float2 a0 = padd(v[0], v[4]), a4 = psub(v[0], v[4]);
    float2 a1 = padd(v[1], v[5]), a5 = psub(v[1], v[5]);
    float2 a2 = padd(v[2], v[6]), a6 = psub(v[2], v[6]);
    float2 a3 = padd(v[3], v[7]), a7 = psub(v[3], v[7]);
    a5 = cmul(a5, make_float2(c, SGN * c));
    a6 = (SGN < 0) ? make_float2(a6.y, -a6.x) : make_float2(-a6.y, a6.x);
    a7 = cmul(a7, make_float2(-c, SGN * c));
    float2 b0 = padd(a0, a2), b2 = psub(a0, a2);
    float2 b1 = padd(a1, a3), b3 = psub(a1, a3);
    b3 = (SGN < 0) ? make_float2(b3.y, -b3.x) : make_float2(-b3.y, b3.x);
    float2 e0 = padd(b0, b1), e1 = psub(b0, b1);
    float2 e2 = padd(b2, b3), e3 = psub(b2, b3);
    float2 d0 = padd(a4, a6), d2 = psub(a4, a6);
    float2 d1 = padd(a5, a7), d3 = psub(a5, a7);
    d3 = (SGN < 0) ? make_float2(d3.y, -d3.x) : make_float2(-d3.y, d3.x);
    float2 o0 = padd(d0, d1), o1 = psub(d0, d1);
    float2 o2 = padd(d2, d3), o3 = psub(d2, d3);
    v[0] = e0; v[4] = e1; v[2] = e2; v[6] = e3;
    v[1] = o0; v[5] = o1; v[3] = o2; v[7] = o3;
}

// 8x8 transpose among 8 consecutive lanes (cluster), 8 float2 regs/lane.
__device__ __forceinline__ void cluster_transpose8(float2 v[8], int lane) {
#pragma unroll
    for (int m = 1; m < 8; m <<= 1) {
        bool hi = (lane & m) != 0;
#pragma unroll
        for (int j = 0; j < 8; j++)
            if ((j & m) == 0 && hi) { float2 t = v[j]; v[j] = v[j | m]; v[j | m] = t; }
#pragma unroll
        for (int j = 0; j < 8; j++)
            if (j & m) {
                f2u t; t.f = v[j];
                t.u = __shfl_xor_sync(0xffffffffu, t.u, m);
                v[j] = t.f;
            }
#pragma unroll
        for (int j = 0; j < 8; j++)
            if ((j & m) == 0 && hi) { float2 t = v[j]; v[j] = v[j | m]; v[j | m] = t; }
    }
}

// ---------------- one-off: precompute twiddle table ----------------
__global__ void twinit() {
    int k = blockIdx.x * 512 + threadIdx.x;
    float sn, cs;
    sincospif(-(float)k / 2048.0f, &sn, &cs);
    g_twg[k] = make_float2(cs, sn);
}

// ---------------- transpose + pack:  [bh][s][d] -> [bh][d][s] as (q, k) float2 ----------------
__global__ void transpose_pack(const float* __restrict__ q, const float* __restrict__ k) {
    __shared__ float qt[32][33];
    __shared__ float kt[32][33];
    int bh = blockIdx.z;
    int s0 = blockIdx.x * 32;
    int d0 = blockIdx.y * 32;
    int tx = threadIdx.x, ty = threadIdx.y;
    const float* qb = q + (size_t)bh * S * D;
    const float* kb = k + (size_t)bh * S * D;
#pragma unroll
    for (int r = 0; r < 4; r++) {
        int s = s0 + ty + r * 8;
        qt[ty + r * 8][tx] = qb[(size_t)s * D + d0 + tx];
        kt[ty + r * 8][tx] = kb[(size_t)s * D + d0 + tx];
    }
    __syncthreads();
#pragma unroll
    for (int r = 0; r < 4; r++) {
        int d = d0 + ty + r * 8;
        int s = s0 + tx;
        g_x[((size_t)bh * D + d) * S + s] = make_float2(qt[tx][ty + r * 8], kt[tx][ty + r * 8]);
    }
}

// ---------------- per-series: radix-8 FFT -> cross-spectrum -> IFFT -> rank-select -> softmax ----------------
__global__ __launch_bounds__(NT, 2) void fft_corr_sort() {
    __shared__ float2 sx[SIDX(S - 1) + 1];      // ~36.9 KB (padded)
    __shared__ float2 s_tw[PIDX(1023) + 1];     // ~8.3 KB padded twiddles; reused for reduce + survivors
    __shared__ int scount;
    int tid = threadIdx.x;
    int lane = tid & 31;
    int grp = tid >> 6;                          // 64-thread group id (0..7)
    const float2* gx = g_x + (size_t)blockIdx.x * S;

    float2 v[8];
    // issue global loads first so their latency overlaps the table load
#pragma unroll
    for (int r = 0; r < 8; r++) v[r] = gx[tid + 512 * r];

    // load precomputed twiddle table (L2-resident after first wave)
#pragma unroll
    for (int k = tid; k < 1024; k += NT) s_tw[PIDX(k)] = g_twg[k];
    __syncthreads();                       // twiddle table ready

    // ---- forward stage 0 : stride 512, p=tid ----
    dft8<-1>(v);
#pragma unroll
    for (int r = 1; r < 8; r++) v[r] = cmul(v[r], twid(s_tw, tid * r));
#pragma unroll
    for (int r = 0; r < 8; r++) sx[SIDX(tid + 512 * r)] = v[r];
    __syncthreads();
    // ---- forward stage 1 : stride 64 (exchange stays within 512-element group) ----
    {
        int base = grp << 9, p = tid & 63;
#pragma unroll
        for (int r = 0; r < 8; r++) v[r] = sx[SIDX(base + p + 64 * r)];
        dft8<-1>(v);
#pragma unroll
        for (int r = 1; r < 8; r++) v[r] = cmul(v[r], twid(s_tw, (p * r) << 3));
#pragma unroll
        for (int r = 0; r < 8; r++) sx[SIDX(base + p + 64 * r)] = v[r];
    }
    barg(grp);                             // group-local handoff only
    // ---- forward stages 2+3 merged: stage-2 in regs, shfl transpose, stage-3 in regs ----
    {
        int base = (tid >> 3) << 6, p = tid & 7;
#pragma unroll
        for (int r = 0; r < 8; r++) v[r] = sx[SIDX(base + p + 8 * r)];
        dft8<-1>(v);
#pragma unroll
        for (int r = 1; r < 8; r++) v[r] = cmul(v[r], twid(s_tw, (p * r) << 6));
        cluster_transpose8(v, lane);
        dft8<-1>(v);                       // stage 3, no twiddle
        // v[e] = spectrum (octal-reversed) at position 8*tid + e ; publish for partner reads
#pragma unroll
        for (int r = 0; r < 8; r++) sx[SIDX(8 * tid + r)] = v[r];
    }
    __syncthreads();

    // ---- cross-spectrum (own 8 positions, partner read only) + inverse stages 0+1 merged ----
    {
        float2 xp[8];
#pragma unroll
        for (int e = 0; e < 8; e++) {
            int j  = 8 * tid + e;
            int f  = rev8(j);
            int fp = (S - f) & (S - 1);
            xp[e] = sx[SIDX(rev8(fp))];
        }
        __syncthreads();                   // all partner reads complete before anyone's inv1 writes
#pragma unroll
        for (int e = 0; e < 8; e++) {
            float2 X = v[e], Xp = xp[e];
            float Qr = 0.5f * (X.x + Xp.x);
            float Qi = 0.5f * (X.y - Xp.y);
            float Kr = 0.5f * (X.y + Xp.y);
            float Ki = 0.5f * (Xp.x - X.x);
            v[e] = make_float2(Qr * Kr + Qi * Ki, Qi * Kr - Qr * Ki);
        }
        dft8<1>(v);                        // inverse stage 0 (contiguous 8, no twiddle)
        cluster_transpose8(v, lane);       // redistribute for stride-8 stage (cluster-local)
        int p = tid & 7;
#pragma unroll
        for (int r = 1; r < 8; r++) v[r] = cmul(v[r], cconj(twid(s_tw, (p * r) << 6)));
        dft8<1>(v);                        // inverse stage 1
        int base = (tid >> 3) << 6;
#pragma unroll
        for (int r = 0; r < 8; r++) sx[SIDX(base + p + 8 * r)] = v[r];
    }
    barg(grp);                             // group-local handoff only
    // ---- inverse stage 2 : stride 64 (within group) ----
    {
        int base = grp << 9, p = tid & 63;
#pragma unroll
        for (int r = 0; r < 8; r++) v[r] = sx[SIDX(base + p + 64 * r)];
#pragma unroll
        for (int r = 1; r < 8; r++) v[r] = cmul(v[r], cconj(twid(s_tw, (p * r) << 3)));
        dft8<1>(v);
#pragma unroll
        for (int r = 0; r < 8; r++) sx[SIDX(base + p + 64 * r)] = v[r];
    }
    __syncthreads();

    // ---- inverse stage 3 : stride 512 ; corr stays in registers ----
    float rv[8];
    {
        const float invN = 1.0f / (float)S;
#pragma unroll
        for (int r = 0; r < 8; r++) v[r] = sx[SIDX(tid + 512 * r)];
#pragma unroll
        for (int r = 1; r < 8; r++) v[r] = cmul(v[r], cconj(twid(s_tw, tid * r)));
        dft8<1>(v);
#pragma unroll
        for (int r = 0; r < 8; r++) rv[r] = v[r].x * invN;
    }
    __syncthreads();                        // all sx / s_tw reads done; reuse s_tw region

    float* red  = (float*)s_tw;             // [0..32) reduction scratch
    float* surv = ((float*)s_tw) + 1024;    // [1024..1536) survivor list (512 floats)

    // ---- block max m ----
    float m = rv[0];
#pragma unroll
    for (int e = 1; e < 8; e++) m = fmaxf(m, rv[e]);
#pragma unroll
    for (int o = 16; o > 0; o >>= 1) m = fmaxf(m, __shfl_xor_sync(0xffffffffu, m, o));
    if ((tid & 31) == 0) red[tid >> 5] = m;
    __syncthreads();
    m = red[0];
#pragma unroll
    for (int i = 1; i < NT / 32; i++) m = fmaxf(m, red[i]);

    // ---- Z over all 4096 (order-free; __expf FTZ zeros the deep tail) ----
    float part = 0.f;
#pragma unroll
    for (int e = 0; e < 8; e++) part += __expf(rv[e] - m);
#pragma unroll
    for (int o = 16; o > 0; o >>= 1) part += __shfl_xor_sync(0xffffffffu, part, o);
    if ((tid & 31) == 0) red[16 + (tid >> 5)] = part;
    if (tid == 0) scount = 0;
    __syncthreads();
    float Z = 0.f;
#pragma unroll
    for (int i = 0; i < NT / 32; i++) Z += red[16 + i];
    float invZ = 1.0f / Z;

    // ---- compact survivors (v >= m-95; anything below has __expf == 0 identically) ----
    float thresh = m - 95.0f;
#pragma unroll
    for (int e = 0; e < 8; e++) {
        if (rv[e] >= thresh) {
            int p = atomicAdd(&scount, 1);
            if (p < K) surv[p] = rv[e];
        }
    }
    __syncthreads();
    int C = scount < K ? scount : K;

    // ---- rank-by-counting (replaces full sort): survivor tid gets rank = #greater (+index tiebreak).
    // Ranks [0,C) are a permutation -> survivors write their weight at their rank;
    // ranks [C,512) have weight exactly 0 -> threads tid>=C zero their own slot.
    float* gw = g_wk + (size_t)blockIdx.x * K;
    if (tid < C) {
        float vv = surv[tid];
        int rank = 0;
        for (int j = 0; j < C; j++) {
            float o = surv[j];                      // broadcast read
            rank += (int)((o > vv) || (o == vv && j < tid));
        }
        gw[rank] = __expf(vv - m) * invZ;
    } else {
        gw[tid] = 0.f;
    }
}

// ---------------- out[bh,i,l] = sum_j Wk[bh,j,i] * V[bh,j,l] for i<K ; zeros for i>=K ----------------
__global__ __launch_bounds__(256) void wgemm(const float* __restrict__ v, float* __restrict__ out) {
    __shared__ float Vs[D * D];
    __shared__ float Ws[D][128];
    int bh  = blockIdx.y;
    int i0  = blockIdx.x * 128;             // blockIdx.x in [0, S/128)
    int tid = threadIdx.x;

    if (i0 >= K) {                          // ranks >= K have softmax weight identically 0
        float4 z = make_float4(0.f, 0.f, 0.f, 0.f);
        float4* ob = (float4*)(out + ((size_t)bh * S + i0) * D);
#pragma unroll
        for (int p = 0; p < (128 * D / 4) / 256; p++) ob[tid + p * 256] = z;
        return;
    }

    const float* vb = v + (size_t)bh * S * D;
#pragma unroll
    for (int p = 0; p < (D * D) / 256; p++) Vs[tid + p * 256] = vb[tid + p * 256];
    const float* wb = g_wk + (size_t)bh * D * K + i0;
#pragma unroll
    for (int p = 0; p < (D * 128) / 256; p++) {
        int q = tid + p * 256;
        int j = q >> 7, i = q & 127;
        Ws[j][i] = wb[(size_t)j * K + i];
    }
    __syncthreads();
    int il = tid & 15, ir = tid >> 4;
    float acc[8][4];
#pragma unroll
    for (int a = 0; a < 8; a++)
#pragma unroll
        for (int b = 0; b < 4; b++) acc[a][b] = 0.f;
#pragma unroll 4
    for (int j = 0; j < D; j++) {
        float4 vl = *(const float4*)&Vs[j * D + il * 4];
        float4 w0 = *(const float4*)&Ws[j][ir * 8];
        float4 w1 = *(const float4*)&Ws[j][ir * 8 + 4];
        float wv[8] = {w0.x, w0.y, w0.z, w0.w, w1.x, w1.y, w1.z, w1.w};
#pragma unroll
        for (int a = 0; a < 8; a++) {
            acc[a][0] += wv[a] * vl.x;
            acc[a][1] += wv[a] * vl.y;
            acc[a][2] += wv[a] * vl.z;
            acc[a][3] += wv[a] * vl.w;
        }
    }
    float* ob = out + ((size_t)bh * S + i0) * D;
#pragma unroll
    for (int a = 0; a < 8; a++) {
        float4 o = make_float4(acc[a][0], acc[a][1], acc[a][2], acc[a][3]);
        *(float4*)&ob[(size_t)(ir * 8 + a) * D + il * 4] = o;
    }
}

extern "C" void kernel_launch(void* const* d_in, const int* in_sizes, int n_in,
                              void* d_out, int out_size) {
    const float* q = (const float*)d_in[0];
    const float* k = (const float*)d_in[1];
    const float* v = (const float*)d_in[2];
    float* out = (float*)d_out;

    twinit<<<2, 512>>>();

    dim3 tb(32, 8);
    dim3 tg(S / 32, D / 32, BH);
    transpose_pack<<<tg, tb>>>(q, k);

    fft_corr_sort<<<BH * D, NT>>>();

    dim3 gg(S / 128, BH);
    wgemm<<<gg, 256>>>(v, out);
}

// round 15
// speedup vs baseline: 1.5199x; 1.0539x over previous
#include <cuda_runtime.h>
#include <math.h>

#define BH   64
#define S    4096
#define D    64
#define NT   512
#define K    512
#define SIDX(a) ((a) + ((a) >> 3))
#define PIDX(e) ((e) + ((e) >> 5))          // twiddle-table anti-bank-conflict padding

// Static scratch (allocation-free rule: __device__ globals)
__device__ float2 g_x[(size_t)BH * D * S];    // packed q + i*k, layout [bh][d][s]
__device__ float  g_wk[(size_t)BH * D * K];   // top-K sorted softmax weights per column (8 MB)
__device__ float2 g_twg[1024];                // precomputed W_4096^k, k in [0,1024)

// ---------------- packed f32x2 complex helpers ----------------
union f2u { float2 f; unsigned long long u; };

__device__ __forceinline__ float2 padd(float2 a, float2 b) {
    f2u A, B, R; A.f = a; B.f = b;
    asm("add.rn.f32x2 %0, %1, %2;" : "=l"(R.u) : "l"(A.u), "l"(B.u));
    return R.f;
}
__device__ __forceinline__ float2 psub(float2 a, float2 b) {
    f2u A, B, R, M; A.f = a; B.f = b; M.f = make_float2(-1.f, -1.f);
    asm("fma.rn.f32x2 %0, %1, %2, %3;" : "=l"(R.u) : "l"(B.u), "l"(M.u), "l"(A.u));
    return R.f;
}
__device__ __forceinline__ float2 cmul(float2 a, float2 b) {
    return make_float2(fmaf(a.x, b.x, -a.y * b.y), fmaf(a.x, b.y, a.y * b.x));
}
__device__ __forceinline__ float2 cconj(float2 a) { return make_float2(a.x, -a.y); }

// named 64-thread barrier for group g (warps 2g, 2g+1); ids 1..8 (0 is __syncthreads)
__device__ __forceinline__ void barg(int g) {
    asm volatile("bar.sync %0, 64;" :: "r"(g + 1) : "memory");
}

// W_4096^e for e in [0, 4096): padded table of 1024 + rotation by (-i)^(e>>10)
__device__ __forceinline__ float2 twid(const float2* __restrict__ T, int e) {
    float2 t = T[PIDX(e & 1023)];
    int q = e >> 10;
    float2 r = t;
    if (q & 1) r = make_float2(r.y, -r.x);
    if (q & 2) r = make_float2(-r.x, -r.y);
    return r;
}

// octal-digit reversal of 12-bit index
__device__ __forceinline__ int rev8(int f) {
    return ((f & 7) << 9) | (((f >> 3) & 7) << 6) | (((f >> 6) & 7) << 3) | ((f >> 9) & 7);
}

// 8-point DFT in registers, natural-order outputs. SGN=-1 forward, +1 inverse.
template<int SGN>
__device__ __forceinline__ void dft8(float2 v[8]) {
    const float c = 0.70710678118654752f;
    float2 a0 = padd(v[0], v[4]), a4 = psub(v[0], v[4]);
    float2 a1 = padd(v[1], v[5]), a5 = psub(v[1], v[5]);
    float2 a2 = padd(v[2], v[6]), a6 = psub(v[2], v[6]);
    float2 a3 = padd(v[3], v[7]), a7 = psub(v[3], v[7]);
    a5 = cmul(a5, make_float2(c, SGN * c));
    a6 = (SGN < 0) ? make_float2(a6.y, -a6.x) : make_float2(-a6.y, a6.x);
    a7 = cmul(a7, make_float2(-c, SGN * c));
    float2 b0 = padd(a0, a2), b2 = psub(a0, a2);
    float2 b1 = padd(a1, a3), b3 = psub(a1, a3);
    b3 = (SGN < 0) ? make_float2(b3.y, -b3.x) : make_float2(-b3.y, b3.x);
    float2 e0 = padd(b0, b1), e1 = psub(b0, b1);
    float2 e2 = padd(b2, b3), e3 = psub(b2, b3);
    float2 d0 = padd(a4, a6), d2 = psub(a4, a6);
    float2 d1 = padd(a5, a7), d3 = psub(a5, a7);
    d3 = (SGN < 0) ? make_float2(d3.y, -d3.x) : make_float2(-d3.y, d3.x);
    float2 o0 = padd(d0, d1), o1 = psub(d0, d1);
    float2 o2 = padd(d2, d3), o3 = psub(d2, d3);
    v[0] = e0; v[4] = e1; v[2] = e2; v[6] = e3;
    v[1] = o0; v[5] = o1; v[3] = o2; v[7] = o3;
}

// ---------------- one-off: precompute twiddle table ----------------
__global__ void twinit() {
    int k = blockIdx.x * 512 + threadIdx.x;
    float sn, cs;
    sincospif(-(float)k / 2048.0f, &sn, &cs);
    g_twg[k] = make_float2(cs, sn);
}

// ---------------- transpose + pack:  [bh][s][d] -> [bh][d][s] as (q, k) float2 ----------------
__global__ void transpose_pack(const float* __restrict__ q, const float* __restrict__ k) {
    __shared__ float qt[32][33];
    __shared__ float kt[32][33];
    int bh = blockIdx.z;
    int s0 = blockIdx.x * 32;
    int d0 = blockIdx.y * 32;
    int tx = threadIdx.x, ty = threadIdx.y;
    const float* qb = q + (size_t)bh * S * D;
    const float* kb = k + (size_t)bh * S * D;
#pragma unroll
    for (int r = 0; r < 4; r++) {
        int s = s0 + ty + r * 8;
        qt[ty + r * 8][tx] = qb[(size_t)s * D + d0 + tx];
        kt[ty + r * 8][tx] = kb[(size_t)s * D + d0 + tx];
    }
    __syncthreads();
#pragma unroll
    for (int r = 0; r < 4; r++) {
        int d = d0 + ty + r * 8;
        int s = s0 + tx;
        g_x[((size_t)bh * D + d) * S + s] = make_float2(qt[tx][ty + r * 8], kt[tx][ty + r * 8]);
    }
}

// ---------------- per-series: radix-8 FFT -> cross-spectrum -> IFFT -> rank-select -> softmax ----------------
__global__ __launch_bounds__(NT, 2) void fft_corr_sort() {
    __shared__ float2 sx[SIDX(S - 1) + 1];      // ~36.9 KB (padded)
    __shared__ float2 s_tw[PIDX(1023) + 1];     // ~8.3 KB padded twiddles; reused for reduce + survivors
    __shared__ int scount;
    int tid = threadIdx.x;
    int grp = tid >> 6;                          // 64-thread group id (0..7)
    const float2* gx = g_x + (size_t)blockIdx.x * S;

    float2 v[8];
    // issue global loads first so their latency overlaps the table load
#pragma unroll
    for (int r = 0; r < 8; r++) v[r] = gx[tid + 512 * r];

    // load precomputed twiddle table (L2-resident after first wave)
#pragma unroll
    for (int k = tid; k < 1024; k += NT) s_tw[PIDX(k)] = g_twg[k];
    __syncthreads();                       // twiddle table ready

    // ---- forward stage 0 : stride 512, p=tid ----
    dft8<-1>(v);
#pragma unroll
    for (int r = 1; r < 8; r++) v[r] = cmul(v[r], twid(s_tw, tid * r));
#pragma unroll
    for (int r = 0; r < 8; r++) sx[SIDX(tid + 512 * r)] = v[r];
    __syncthreads();
    // ---- forward stage 1 : stride 64 (exchange stays within 512-element group) ----
    {
        int base = grp << 9, p = tid & 63;
#pragma unroll
        for (int r = 0; r < 8; r++) v[r] = sx[SIDX(base + p + 64 * r)];
        dft8<-1>(v);
#pragma unroll
        for (int r = 1; r < 8; r++) v[r] = cmul(v[r], twid(s_tw, (p * r) << 3));
#pragma unroll
        for (int r = 0; r < 8; r++) sx[SIDX(base + p + 64 * r)] = v[r];
    }
    barg(grp);                             // group-local handoff only
    // ---- forward stages 2+3: stage-2 in regs, cluster-local smem exchange, stage-3 in regs ----
    {
        int base = (tid >> 3) << 6, p = tid & 7;
#pragma unroll
        for (int r = 0; r < 8; r++) v[r] = sx[SIDX(base + p + 8 * r)];
        dft8<-1>(v);
#pragma unroll
        for (int r = 1; r < 8; r++) v[r] = cmul(v[r], twid(s_tw, (p * r) << 6));
        // 64-elem sub-block owned by 8 same-warp lanes: smem exchange, warp-sync only
#pragma unroll
        for (int r = 0; r < 8; r++) sx[SIDX(base + p + 8 * r)] = v[r];
        __syncwarp();
#pragma unroll
        for (int r = 0; r < 8; r++) v[r] = sx[SIDX(base + 8 * p + r)];
        dft8<-1>(v);                       // stage 3, no twiddle
        // v[e] = spectrum (octal-reversed) at position 8*tid + e ; publish for partner reads
#pragma unroll
        for (int r = 0; r < 8; r++) sx[SIDX(8 * tid + r)] = v[r];
    }
    __syncthreads();

    // ---- cross-spectrum (own 8 positions, partner read only) + inverse stages 0+1 ----
    {
        float2 xp[8];
#pragma unroll
        for (int e = 0; e < 8; e++) {
            int j  = 8 * tid + e;
            int f  = rev8(j);
            int fp = (S - f) & (S - 1);
            xp[e] = sx[SIDX(rev8(fp))];
        }
        __syncthreads();                   // all partner reads complete before overwrites
#pragma unroll
        for (int e = 0; e < 8; e++) {
            float2 X = v[e], Xp = xp[e];
            float Qr = 0.5f * (X.x + Xp.x);
            float Qi = 0.5f * (X.y - Xp.y);
            float Kr = 0.5f * (X.y + Xp.y);
            float Ki = 0.5f * (Xp.x - X.x);
            v[e] = make_float2(Qr * Kr + Qi * Ki, Qi * Kr - Qr * Ki);
        }
        dft8<1>(v);                        // inverse stage 0 (contiguous 8, no twiddle)
        // redistribute for stride-8 stage: cluster-local smem exchange (same-warp lanes)
        int base = (tid >> 3) << 6, p = tid & 7;
#pragma unroll
        for (int e = 0; e < 8; e++) sx[SIDX(8 * tid + e)] = v[e];
        __syncwarp();
#pragma unroll
        for (int r = 0; r < 8; r++) v[r] = sx[SIDX(base + p + 8 * r)];
#pragma unroll
        for (int r = 1; r < 8; r++) v[r] = cmul(v[r], cconj(twid(s_tw, (p * r) << 6)));
        dft8<1>(v);                        // inverse stage 1
#pragma unroll
        for (int r = 0; r < 8; r++) sx[SIDX(base + p + 8 * r)] = v[r];
    }
    barg(grp);                             // group-local handoff only
    // ---- inverse stage 2 : stride 64 (within group) ----
    {
        int base = grp << 9, p = tid & 63;
#pragma unroll
        for (int r = 0; r < 8; r++) v[r] = sx[SIDX(base + p + 64 * r)];
#pragma unroll
        for (int r = 1; r < 8; r++) v[r] = cmul(v[r], cconj(twid(s_tw, (p * r) << 3)));
        dft8<1>(v);
#pragma unroll
        for (int r = 0; r < 8; r++) sx[SIDX(base + p + 64 * r)] = v[r];
    }
    __syncthreads();

    // ---- inverse stage 3 : stride 512 ; corr stays in registers ----
    float rv[8];
    {
        const float invN = 1.0f / (float)S;
#pragma unroll
        for (int r = 0; r < 8; r++) v[r] = sx[SIDX(tid + 512 * r)];
#pragma unroll
        for (int r = 1; r < 8; r++) v[r] = cmul(v[r], cconj(twid(s_tw, tid * r)));
        dft8<1>(v);
#pragma unroll
        for (int r = 0; r < 8; r++) rv[r] = v[r].x * invN;
    }
    __syncthreads();                        // all sx / s_tw reads done; reuse s_tw region

    float* red  = (float*)s_tw;             // [0..32) reduction scratch
    float* surv = ((float*)s_tw) + 1024;    // [1024..1536) survivor list (512 floats)

    // ---- block max m ----
    float m = rv[0];
#pragma unroll
    for (int e = 1; e < 8; e++) m = fmaxf(m, rv[e]);
#pragma unroll
    for (int o = 16; o > 0; o >>= 1) m = fmaxf(m, __shfl_xor_sync(0xffffffffu, m, o));
    if ((tid & 31) == 0) red[tid >> 5] = m;
    __syncthreads();
    m = red[0];
#pragma unroll
    for (int i = 1; i < NT / 32; i++) m = fmaxf(m, red[i]);

    // ---- Z over all 4096 (order-free; __expf FTZ zeros the deep tail) ----
    float part = 0.f;
#pragma unroll
    for (int e = 0; e < 8; e++) part += __expf(rv[e] - m);
#pragma unroll
    for (int o = 16; o > 0; o >>= 1) part += __shfl_xor_sync(0xffffffffu, part, o);
    if ((tid & 31) == 0) red[16 + (tid >> 5)] = part;
    if (tid == 0) scount = 0;
    __syncthreads();
    float Z = 0.f;
#pragma unroll
    for (int i = 0; i < NT / 32; i++) Z += red[16 + i];
    float invZ = 1.0f / Z;

    // ---- compact survivors (v >= m-95; anything below has __expf == 0 identically) ----
    float thresh = m - 95.0f;
#pragma unroll
    for (int e = 0; e < 8; e++) {
        if (rv[e] >= thresh) {
            int p = atomicAdd(&scount, 1);
            if (p < K) surv[p] = rv[e];
        }
    }
    __syncthreads();
    int C = scount < K ? scount : K;

    // ---- rank-by-counting: survivor tid gets rank = #greater (+index tiebreak) ----
    float* gw = g_wk + (size_t)blockIdx.x * K;
    if (tid < C) {
        float vv = surv[tid];
        int rank = 0;
        for (int j = 0; j < C; j++) {
            float o = surv[j];                      // broadcast read
            rank += (int)((o > vv) || (o == vv && j < tid));
        }
        gw[rank] = __expf(vv - m) * invZ;
    } else {
        gw[tid] = 0.f;
    }
}

// ---------------- out[bh,i,l] = sum_j Wk[bh,j,i] * V[bh,j,l] for i<K ; zeros for i>=K ----------------
__global__ __launch_bounds__(256) void wgemm(const float* __restrict__ v, float* __restrict__ out) {
    __shared__ float Vs[D * D];                 // 16 KB
    __shared__ float Ws[D][64];                 // 16 KB
    int bh  = blockIdx.y;
    int i0  = blockIdx.x * 64;                  // blockIdx.x in [0, S/64)
    int tid = threadIdx.x;

    if (i0 >= K) {                              // ranks >= K have softmax weight identically 0
        float4 z = make_float4(0.f, 0.f, 0.f, 0.f);
        float4* ob = (float4*)(out + ((size_t)bh * S + i0) * D);
#pragma unroll
        for (int p = 0; p < (64 * D / 4) / 256; p++) ob[tid + p * 256] = z;
        return;
    }

    const float* vb = v + (size_t)bh * S * D;
#pragma unroll
    for (int p = 0; p < (D * D) / 256; p++) Vs[tid + p * 256] = vb[tid + p * 256];
    const float* wb = g_wk + (size_t)bh * D * K + i0;
#pragma unroll
    for (int p = 0; p < (D * 64) / 256; p++) {
        int q = tid + p * 256;
        int j = q >> 6, i = q & 63;
        Ws[j][i] = wb[(size_t)j * K + i];
    }
    __syncthreads();
    int il = tid & 15, ir = tid >> 4;           // l-tile of 4, i-tile of 4
    float acc[4][4];
#pragma unroll
    for (int a = 0; a < 4; a++)
#pragma unroll
        for (int b = 0; b < 4; b++) acc[a][b] = 0.f;
#pragma unroll 4
    for (int j = 0; j < D; j++) {
        float4 vl = *(const float4*)&Vs[j * D + il * 4];
        float4 w  = *(const float4*)&Ws[j][ir * 4];
        float wv[4] = {w.x, w.y, w.z, w.w};
#pragma unroll
        for (int a = 0; a < 4; a++) {
            acc[a][0] += wv[a] * vl.x;
            acc[a][1] += wv[a] * vl.y;
            acc[a][2] += wv[a] * vl.z;
            acc[a][3] += wv[a] * vl.w;
        }
    }
    float* ob = out + ((size_t)bh * S + i0) * D;
#pragma unroll
    for (int a = 0; a < 4; a++) {
        float4 o = make_float4(acc[a][0], acc[a][1], acc[a][2], acc[a][3]);
        *(float4*)&ob[(size_t)(ir * 4 + a) * D + il * 4] = o;
    }
}

extern "C" void kernel_launch(void* const* d_in, const int* in_sizes, int n_in,
                              void* d_out, int out_size) {
    const float* q = (const float*)d_in[0];
    const float* k = (const float*)d_in[1];
    const float* v = (const float*)d_in[2];
    float* out = (float*)d_out;

    twinit<<<2, 512>>>();

    dim3 tb(32, 8);
    dim3 tg(S / 32, D / 32, BH);
    transpose_pack<<<tg, tb>>>(q, k);

    fft_corr_sort<<<BH * D, NT>>>();

    dim3 gg(S / 64, BH);
    wgemm<<<gg, 256>>>(v, out);
}